// round 4
// baseline (speedup 1.0000x reference)
#include <cuda_runtime.h>
#include <math.h>
#include <float.h>

#define BQ    8192
#define NB    2
#define NQ    (NB*BQ)
#define KNN   16
#define BALL2 0.2f
#define GR    10
#define GC    (GR*GR*GR)
#define HCELL 0.1f
#define NBLK  256

// ---------------- scratch (no allocations allowed) ----------------
__device__ float4 g_db[NQ];          // packed ref points, input order
__device__ float4 g_ppk[NQ];         // packed pts, input order
__device__ int    g_pcell[NQ];
__device__ int    g_start[NB][GC+1];
__device__ float4 g_spts[NQ];        // cell-sorted ref (x,y,z,-0.5*||p||^2)
__device__ int    g_sidx[NQ];        // original local index of sorted point
__device__ double g_partial[NBLK];
__device__ int    g_done;

__device__ __forceinline__ int cid1(float v) {
    int c = (int)(v * (float)GR);
    return min(GR - 1, max(c, 0));
}

// ================= fused grid build: pack + count + scan + scatter =================
__global__ void __launch_bounds__(1024) build_kernel(
    const float* __restrict__ ref, const float* __restrict__ pts) {
    __shared__ int scnt[GC];
    __shared__ int sscan[GC];
    __shared__ int scur[GC];
    const int b = blockIdx.x;
    const int t = threadIdx.x;
    if (b == 0 && t == 0) g_done = 0;

    if (t < GC) scnt[t] = 0;
    __syncthreads();

    const float* rp = ref + (size_t)b * BQ * 3;
    const float* pp = pts + (size_t)b * BQ * 3;
#pragma unroll
    for (int k = 0; k < 8; k++) {
        const int i = k * 1024 + t;
        const float x = rp[3*i+0], y = rp[3*i+1], z = rp[3*i+2];
        const float n = x*x + y*y + z*z;
        g_db[b*BQ + i] = make_float4(x, y, z, -0.5f*n);
        g_ppk[b*BQ + i] = make_float4(pp[3*i+0], pp[3*i+1], pp[3*i+2], 0.0f);
        const int cell = (cid1(z) * GR + cid1(y)) * GR + cid1(x);
        g_pcell[b*BQ + i] = cell;
        atomicAdd(&scnt[cell], 1);
    }
    __syncthreads();

    // inclusive scan over GC counts (uniform barriers)
    if (t < GC) sscan[t] = scnt[t];
    __syncthreads();
    for (int off = 1; off < GC; off <<= 1) {
        int v = 0;
        if (t < GC && t >= off) v = sscan[t - off];
        __syncthreads();
        if (t < GC) sscan[t] += v;
        __syncthreads();
    }
    if (t < GC) {
        g_start[b][t + 1] = sscan[t];
        scur[t] = sscan[t] - scnt[t];
    }
    if (t == 0) g_start[b][0] = 0;
    __syncthreads();

#pragma unroll
    for (int k = 0; k < 8; k++) {
        const int i = k * 1024 + t;
        const int cell = g_pcell[b*BQ + i];
        const int pos = atomicAdd(&scur[cell], 1);
        g_spts[b*BQ + pos] = g_db[b*BQ + i];
        g_sidx[b*BQ + pos] = i;
    }
}

// ---------------- 3x3 symmetric eigen -> condition ratio (fp32) ----------------
__device__ __forceinline__ float cond_of_gram(
    float g00, float g01, float g02, float g11, float g12, float g22) {
    const float q  = (g00 + g11 + g22) * (1.0f/3.0f);
    const float p1 = g01*g01 + g02*g02 + g12*g12;
    const float b00 = g00 - q, b11 = g11 - q, b22 = g22 - q;
    const float p2 = b00*b00 + b11*b11 + b22*b22 + 2.0f*p1;
    float l0, l2;
    if (p2 <= 0.0f) {
        l0 = q; l2 = q;
    } else {
        const float p   = sqrtf(p2 * (1.0f/6.0f));
        const float inv = 1.0f / p;
        const float c00 = b00*inv, c01 = g01*inv, c02 = g02*inv;
        const float c11 = b11*inv, c12 = g12*inv, c22 = b22*inv;
        float detB = c00*(c11*c22 - c12*c12)
                   - c01*(c01*c22 - c12*c02)
                   + c02*(c01*c12 - c11*c02);
        float r = 0.5f * detB;
        r = fminf(1.0f, fmaxf(-1.0f, r));
        const float phi = acosf(r) * (1.0f/3.0f);
        l0 = q + 2.0f*p*cosf(phi);
        l2 = q + 2.0f*p*cosf(phi + 2.0943951023931953f);
    }
    const float s0 = sqrtf(fmaxf(l0, 0.0f));
    const float s2 = sqrtf(fmaxf(l2, 0.0f));
    return s0 / (s2 + s0);
}

// ================= fused knn + cond + reduction =================
__global__ void __launch_bounds__(256, 3) knncond_kernel(float* __restrict__ out) {
    __shared__ float  sdist[64 * KNN];
    __shared__ int    sind [64 * KNN];
    __shared__ double ssum [64];
    __shared__ double sred [NBLK];
    __shared__ int    sdone;

    const int tid = threadIdx.x;
    const int lg  = tid & 3;
    const int qs  = tid >> 2;
    const unsigned gmask = 0xFu << (tid & 28);   // this 4-lane group's mask
    const int blk = blockIdx.x;
    const int b   = blk >> 7;
    const int s   = b * BQ + (blk & 127) * 64 + qs;

    const float4 qp = g_spts[s];
    const float qx = qp.x, qy = qp.y, qz = qp.z;
    const float qn = -2.0f * qp.w;
    const int cx = cid1(qx), cy = cid1(qy), cz = cid1(qz);

    const float4* __restrict__ sp  = g_spts + b * BQ;
    const int*    __restrict__ si  = g_sidx + b * BQ;
    const float4* __restrict__ ppk = g_ppk  + b * BQ;
    const int*    __restrict__ st  = g_start[b];

    float dv[KNN];
    int   iv[KNN];

    for (int r = 1; r <= GR; ++r) {
#pragma unroll
        for (int j = 0; j < KNN; j++) { dv[j] = FLT_MAX; iv[j] = 0x7fffffff; }
        float tcut = -FLT_MAX;

        const int zlo = max(cz - r, 0), zhi = min(cz + r, GR - 1);
        const int ylo = max(cy - r, 0), yhi = min(cy + r, GR - 1);
        const int xlo = max(cx - r, 0), xhi = min(cx + r, GR - 1);

        for (int zz = zlo; zz <= zhi; zz++) {
            for (int yy = ylo; yy <= yhi; yy++) {
                const int rowbase = (zz * GR + yy) * GR;
                const int j0 = st[rowbase + xlo];
                const int j1 = st[rowbase + xhi + 1];
                for (int j = j0 + lg; j < j1; j += 4) {
                    const float4 p = sp[j];
                    const float t = fmaf(qx, p.x, fmaf(qy, p.y, fmaf(qz, p.z, p.w)));
                    if (t > tcut) {
                        const float d2 = fmaf(-2.0f, t, qn);
                        if (d2 < dv[KNN-1]) {
                            dv[KNN-1] = d2; iv[KNN-1] = j;     // store SORTED index
#pragma unroll
                            for (int m = KNN-1; m > 0; --m) {
                                if (dv[m] < dv[m-1]) {
                                    float td = dv[m]; dv[m] = dv[m-1]; dv[m-1] = td;
                                    int   ti = iv[m]; iv[m] = iv[m-1]; iv[m-1] = ti;
                                }
                            }
                            tcut = 0.5f * (qn - dv[KNN-1]);
                        }
                    }
                }
            }
        }

        // merge 4 sorted lane lists -> exact union top-16
        float kth = FLT_MAX;
        for (int m = 0; m < KNN; m++) {
            float bd = dv[0]; int bi = iv[0];
#pragma unroll
            for (int off = 1; off < 4; off <<= 1) {
                const float od = __shfl_xor_sync(gmask, bd, off, 4);
                const int   oi = __shfl_xor_sync(gmask, bi, off, 4);
                if (od < bd || (od == bd && oi < bi)) { bd = od; bi = oi; }
            }
            if (dv[0] == bd && iv[0] == bi) {
#pragma unroll
                for (int j = 0; j < KNN-1; j++) { dv[j] = dv[j+1]; iv[j] = iv[j+1]; }
                dv[KNN-1] = FLT_MAX; iv[KNN-1] = 0x7fffffff;
            }
            if (lg == 0) { sdist[qs*KNN + m] = bd; sind[qs*KNN + m] = bi; }
            kth = bd;
        }

        float g = FLT_MAX;
        if (cx - r > 0)      g = fminf(g, qx - (float)(cx - r) * HCELL);
        if (cx + r < GR - 1) g = fminf(g, (float)(cx + r + 1) * HCELL - qx);
        if (cy - r > 0)      g = fminf(g, qy - (float)(cy - r) * HCELL);
        if (cy + r < GR - 1) g = fminf(g, (float)(cy + r + 1) * HCELL - qy);
        if (cz - r > 0)      g = fminf(g, qz - (float)(cz - r) * HCELL);
        if (cz + r < GR - 1) g = fminf(g, (float)(cz + r + 1) * HCELL - qz);

        if (g == FLT_MAX || kth < g * g) break;
    }
    __syncthreads();

    // ---- cond phase: 4 lanes per query, shifted-Gram accumulation ----
    {
        float nb = 0.0f;
        float S0r=0.f,S1r=0.f,S2r=0.f, G00r=0.f,G01r=0.f,G02r=0.f,G11r=0.f,G12r=0.f,G22r=0.f;
        float S0p=0.f,S1p=0.f,S2p=0.f, G00p=0.f,G01p=0.f,G02p=0.f,G11p=0.f,G12p=0.f,G22p=0.f;
#pragma unroll
        for (int kk = 0; kk < 4; kk++) {
            const int k = lg + kk * 4;
            const float d = sdist[qs*KNN + k];
            const int   j = sind [qs*KNN + k];
            const float m = (d < BALL2) ? 1.0f : 0.0f;
            nb += m;
            // ref branch: row = m*p, shifted by q -> u = m*p - q
            const float4 pr = sp[j];
            const float ux = fmaf(m, pr.x, -qx);
            const float uy = fmaf(m, pr.y, -qy);
            const float uz = fmaf(m, pr.z, -qz);
            S0r += ux; S1r += uy; S2r += uz;
            G00r += ux*ux; G01r += ux*uy; G02r += ux*uz;
            G11r += uy*uy; G12r += uy*uz; G22r += uz*uz;
            // points branch: unmasked row, u = p - q
            const int id = si[j];
            const float4 pq = ppk[id];
            const float vx = pq.x - qx;
            const float vy = pq.y - qy;
            const float vz = pq.z - qz;
            S0p += vx; S1p += vy; S2p += vz;
            G00p += vx*vx; G01p += vx*vy; G02p += vx*vz;
            G11p += vy*vy; G12p += vy*vz; G22p += vz*vz;
        }
        // 4-lane butterfly reduce of 19 partials
#pragma unroll
        for (int off = 1; off < 4; off <<= 1) {
            nb   += __shfl_xor_sync(gmask, nb,   off, 4);
            S0r  += __shfl_xor_sync(gmask, S0r,  off, 4);
            S1r  += __shfl_xor_sync(gmask, S1r,  off, 4);
            S2r  += __shfl_xor_sync(gmask, S2r,  off, 4);
            G00r += __shfl_xor_sync(gmask, G00r, off, 4);
            G01r += __shfl_xor_sync(gmask, G01r, off, 4);
            G02r += __shfl_xor_sync(gmask, G02r, off, 4);
            G11r += __shfl_xor_sync(gmask, G11r, off, 4);
            G12r += __shfl_xor_sync(gmask, G12r, off, 4);
            G22r += __shfl_xor_sync(gmask, G22r, off, 4);
            S0p  += __shfl_xor_sync(gmask, S0p,  off, 4);
            S1p  += __shfl_xor_sync(gmask, S1p,  off, 4);
            S2p  += __shfl_xor_sync(gmask, S2p,  off, 4);
            G00p += __shfl_xor_sync(gmask, G00p, off, 4);
            G01p += __shfl_xor_sync(gmask, G01p, off, 4);
            G02p += __shfl_xor_sync(gmask, G02p, off, 4);
            G11p += __shfl_xor_sync(gmask, G11p, off, 4);
            G12p += __shfl_xor_sync(gmask, G12p, off, 4);
            G22p += __shfl_xor_sync(gmask, G22p, off, 4);
        }
        if (lg == 0) {
            const float invn = 1.0f / nb;
            const float ex = (16.0f - nb);
            // ref branch: cu = (Su + (16-nb)*q)/nb ; Gram = Suu' - cu Su' - Su cu' + 16 cu cu'
            {
                const float c0 = (S0r + ex*qx) * invn;
                const float c1 = (S1r + ex*qy) * invn;
                const float c2 = (S2r + ex*qz) * invn;
                G00r = G00r - 2.f*c0*S0r + 16.f*c0*c0;
                G11r = G11r - 2.f*c1*S1r + 16.f*c1*c1;
                G22r = G22r - 2.f*c2*S2r + 16.f*c2*c2;
                G01r = G01r - c0*S1r - c1*S0r + 16.f*c0*c1;
                G02r = G02r - c0*S2r - c2*S0r + 16.f*c0*c2;
                G12r = G12r - c1*S2r - c2*S1r + 16.f*c1*c2;
            }
            const float cond_ref = cond_of_gram(G00r,G01r,G02r,G11r,G12r,G22r);
            {
                const float c0 = (S0p + ex*qx) * invn;
                const float c1 = (S1p + ex*qy) * invn;
                const float c2 = (S2p + ex*qz) * invn;
                G00p = G00p - 2.f*c0*S0p + 16.f*c0*c0;
                G11p = G11p - 2.f*c1*S1p + 16.f*c1*c1;
                G22p = G22p - 2.f*c2*S2p + 16.f*c2*c2;
                G01p = G01p - c0*S1p - c1*S0p + 16.f*c0*c1;
                G02p = G02p - c0*S2p - c2*S0p + 16.f*c0*c2;
                G12p = G12p - c1*S2p - c2*S1p + 16.f*c1*c2;
            }
            const float cond_p = cond_of_gram(G00p,G01p,G02p,G11p,G12p,G22p);
            const double diff = (double)cond_p - (double)cond_ref;
            ssum[qs] = diff * diff;
        }
    }
    __syncthreads();

    // block tree-reduce 64 doubles
    for (int stp = 32; stp > 0; stp >>= 1) {
        if (tid < stp) ssum[tid] += ssum[tid + stp];
        __syncthreads();
    }
    if (tid == 0) g_partial[blk] = ssum[0];

    // last-block deterministic final reduction
    if (tid == 0) {
        __threadfence();
        const int v = atomicAdd(&g_done, 1);
        sdone = (v == NBLK - 1);
    }
    __syncthreads();
    if (sdone) {
        __threadfence();
        sred[tid] = g_partial[tid];
        __syncthreads();
        for (int stp = 128; stp > 0; stp >>= 1) {
            if (tid < stp) sred[tid] += sred[tid + stp];
            __syncthreads();
        }
        if (tid == 0) out[0] = (float)(sred[0] / (double)NQ);
    }
}

// ---------------- launch ----------------
extern "C" void kernel_launch(void* const* d_in, const int* in_sizes, int n_in,
                              void* d_out, int out_size) {
    const float* ref = (const float*)d_in[0];
    const float* pts = (const float*)d_in[1];
    build_kernel<<<NB, 1024>>>(ref, pts);
    knncond_kernel<<<NBLK, 256>>>((float*)d_out);
}